// round 2
// baseline (speedup 1.0000x reference)
#include <cuda_runtime.h>
#include <cstdint>
#include <cstddef>

#define HID   4096
#define LQ    128
#define CTXN  896
#define TT    1024
#define STATE 3072
#define HQ    32
#define HKV   8
#define DH    128
#define SCALE 0.08838834764831845f
#define NEPS  1e-6f

// ---------------- scratch (device globals; no allocation APIs) ----------------
__device__ float g_q [LQ * HID];       // q projection  [L][HQ*D]
__device__ float g_qr[HQ * LQ * DH];   // q normed+roped+scaled [HQ][L][D]
__device__ float g_k [TT * HKV * DH];  // k projection  [T][HKV*D]
__device__ float g_v [TT * HKV * DH];  // v projection  [T][HKV*D]
__device__ float g_o [LQ * HID];       // attention out [L][HQ*D]

// ---------------- packed f32x2 helpers ----------------
static __device__ __forceinline__ unsigned long long pk2(float x) {
    unsigned long long r; unsigned u = __float_as_uint(x);
    asm("mov.b64 %0, {%1, %1};" : "=l"(r) : "r"(u));
    return r;
}
static __device__ __forceinline__ void fma2(unsigned long long& c,
                                            unsigned long long a,
                                            unsigned long long b) {
    asm("fma.rn.f32x2 %0, %1, %2, %0;" : "+l"(c) : "l"(a), "l"(b));
}
static __device__ __forceinline__ unsigned long long mul2(unsigned long long a,
                                                          unsigned long long b) {
    unsigned long long d;
    asm("mul.rn.f32x2 %0, %1, %2;" : "=l"(d) : "l"(a), "l"(b));
    return d;
}
static __device__ __forceinline__ float2 up2(unsigned long long v) {
    unsigned lo, hi;
    asm("mov.b64 {%0, %1}, %2;" : "=r"(lo), "=r"(hi) : "l"(v));
    return make_float2(__uint_as_float(lo), __uint_as_float(hi));
}

// ---------------- GEMM: C[M,N] = A[M,K=4096] * B[N,K]^T ----------------
// BM=64, BN=128, BK=16, 256 threads, 4m x 8n micro-tile in f32x2.
// which: 0 -> C=g_q, A=split(A0|A1)
//        1 -> C=(z? g_v : g_k), B=(z? B1 : B0), A=split(A0|A1)
//        2 -> C=Cext, A=g_o
__global__ __launch_bounds__(256) void gemm_k(
    int which,
    const float* __restrict__ A0, const float* __restrict__ A1, int split,
    const float* __restrict__ B0, const float* __restrict__ B1,
    float* __restrict__ Cext, int N)
{
    __shared__ float As[16][68];
    __shared__ float Bs[16][132];

    const int tid  = threadIdx.x;
    const int m0   = blockIdx.y * 64;
    const int n0   = blockIdx.x * 128;
    const int z    = blockIdx.z;
    const float* B = z ? B1 : B0;
    float* C;
    if      (which == 0) C = g_q;
    else if (which == 1) C = z ? g_v : g_k;
    else                 C = Cext;

    const int arow = tid >> 2, ac4 = tid & 3;
    const int ty   = tid >> 4, tx  = tid & 15;

    unsigned long long acc[4][4];
#pragma unroll
    for (int i = 0; i < 4; i++)
#pragma unroll
        for (int j = 0; j < 4; j++) acc[i][j] = 0ULL;

    const int am = m0 + arow;
    const float* ap;
    if (which == 2) ap = g_o + (size_t)am * 4096;
    else            ap = (am < split) ? (A0 + (size_t)am * 4096)
                                      : (A1 + (size_t)(am - split) * 4096);
    const float* bp0 = B + (size_t)(n0 + arow) * 4096;
    const float* bp1 = B + (size_t)(n0 + 64 + arow) * 4096;

    for (int k0 = 0; k0 < 4096; k0 += 16) {
        float4 av = *(const float4*)(ap  + k0 + ac4 * 4);
        float4 b0 = *(const float4*)(bp0 + k0 + ac4 * 4);
        float4 b1 = *(const float4*)(bp1 + k0 + ac4 * 4);
        __syncthreads();
        As[ac4*4+0][arow] = av.x; As[ac4*4+1][arow] = av.y;
        As[ac4*4+2][arow] = av.z; As[ac4*4+3][arow] = av.w;
        Bs[ac4*4+0][arow] = b0.x; Bs[ac4*4+1][arow] = b0.y;
        Bs[ac4*4+2][arow] = b0.z; Bs[ac4*4+3][arow] = b0.w;
        Bs[ac4*4+0][64+arow] = b1.x; Bs[ac4*4+1][64+arow] = b1.y;
        Bs[ac4*4+2][64+arow] = b1.z; Bs[ac4*4+3][64+arow] = b1.w;
        __syncthreads();
#pragma unroll
        for (int kk = 0; kk < 16; kk++) {
            float4 a = *(const float4*)&As[kk][ty * 4];
            unsigned long long ad[4] = { pk2(a.x), pk2(a.y), pk2(a.z), pk2(a.w) };
            unsigned long long bb[4];
#pragma unroll
            for (int j = 0; j < 4; j++)
                bb[j] = *(const unsigned long long*)&Bs[kk][2 * tx + 32 * j];
#pragma unroll
            for (int i = 0; i < 4; i++)
#pragma unroll
                for (int j = 0; j < 4; j++) fma2(acc[i][j], ad[i], bb[j]);
        }
    }
#pragma unroll
    for (int i = 0; i < 4; i++) {
        int m = m0 + ty * 4 + i;
        float* cr = C + (size_t)m * N + n0;
#pragma unroll
        for (int j = 0; j < 4; j++) {
            float2 p = up2(acc[i][j]);
            *(float2*)&cr[2 * tx + 32 * j] = p;
        }
    }
}

// ---------------- ane-norm + RoPE + scale for Q ----------------
__global__ __launch_bounds__(128) void qnorm_k(
    const float* __restrict__ cq, const float* __restrict__ sq,
    const float* __restrict__ w)
{
    int h = blockIdx.x, l = blockIdx.y, d = threadIdx.x;
    __shared__ float red[8];
    __shared__ float xs[128];
    float v = g_q[l * HID + h * DH + d];
    float s1 = v, s2 = v * v;
#pragma unroll
    for (int off = 16; off; off >>= 1) {
        s1 += __shfl_down_sync(0xffffffffu, s1, off);
        s2 += __shfl_down_sync(0xffffffffu, s2, off);
    }
    if ((d & 31) == 0) { red[d >> 5] = s1; red[4 + (d >> 5)] = s2; }
    __syncthreads();
    float sum = red[0] + red[1] + red[2] + red[3];
    float sqs = red[4] + red[5] + red[6] + red[7];
    float mean = sum * (1.0f / 128.0f);
    float var  = sqs * (1.0f / 128.0f) - mean * mean;
    float xn = (v - mean) * rsqrtf(var + NEPS) * w[d];
    xs[d] = xn;
    __syncthreads();
    float rot = (d < 64) ? -xs[d + 64] : xs[d - 64];
    g_qr[((size_t)h * LQ + l) * DH + d] =
        (xn * cq[l * DH + d] + rot * sq[l * DH + d]) * SCALE;
}

// ---------------- ane-norm + RoPE for K, transpose K/V -> [HKV][T][D] ----------------
__global__ __launch_bounds__(128) void kvnorm_k(
    const float* __restrict__ ck, const float* __restrict__ sk,
    const float* __restrict__ w,
    float* __restrict__ kOut, float* __restrict__ vOut)
{
    int h = blockIdx.x, t = blockIdx.y, d = threadIdx.x;
    __shared__ float red[8];
    __shared__ float xs[128];
    float v = g_k[t * (HKV * DH) + h * DH + d];
    float s1 = v, s2 = v * v;
#pragma unroll
    for (int off = 16; off; off >>= 1) {
        s1 += __shfl_down_sync(0xffffffffu, s1, off);
        s2 += __shfl_down_sync(0xffffffffu, s2, off);
    }
    if ((d & 31) == 0) { red[d >> 5] = s1; red[4 + (d >> 5)] = s2; }
    __syncthreads();
    float sum = red[0] + red[1] + red[2] + red[3];
    float sqs = red[4] + red[5] + red[6] + red[7];
    float mean = sum * (1.0f / 128.0f);
    float var  = sqs * (1.0f / 128.0f) - mean * mean;
    float xn = (v - mean) * rsqrtf(var + NEPS) * w[d];
    xs[d] = xn;
    __syncthreads();
    float rot = (d < 64) ? -xs[d + 64] : xs[d - 64];
    kOut[((size_t)h * TT + t) * DH + d] = xn * ck[t * DH + d] + rot * sk[t * DH + d];
    vOut[((size_t)h * TT + t) * DH + d] = g_v[t * (HKV * DH) + h * DH + d];
}

// ---------------- Flash attention (fp32, f32x2 inner loops) ----------------
// grid (32 heads, 4 q-tiles of 32). 256 threads. K and V share sKV (swizzled quads).
static __device__ __forceinline__ int swf(int r, int f) {  // f even
    return ((((f >> 2) + r) & 31) << 2) | (f & 3);
}
__global__ __launch_bounds__(256) void attn_k(
    const float* __restrict__ cK, const float* __restrict__ cV,
    const float* __restrict__ kN, const float* __restrict__ vN)
{
    const int h = blockIdx.x, qt = blockIdx.y;
    const int g = h >> 2, l0 = qt * 32, tid = threadIdx.x;

    __shared__ float sQ [32][132];
    __shared__ float sKV[32][128];
    __shared__ float sS [32][33];
    __shared__ float sM[32], sL[32], sC[32];

    for (int idx = tid; idx < 32 * 32; idx += 256) {
        int r = idx >> 5, c4 = idx & 31;
        *(float4*)&sQ[r][c4 * 4] =
            *(const float4*)&g_qr[((size_t)h * LQ + l0 + r) * DH + c4 * 4];
    }
    if (tid < 32) { sM[tid] = -1e30f; sL[tid] = 0.0f; }

    const int ldr = tid >> 3, ldf = tid & 7;   // tile loads
    const int ty  = tid >> 4, tx  = tid & 15;  // scores: rows {ty,ty+16}, cols {tx,tx+16}
    const int pr  = tid >> 4, pd  = tid & 15;  // PV: rows {pr,pr+16}, d = 2*pd + 32*j

    unsigned long long acc[2][4];
#pragma unroll
    for (int i = 0; i < 2; i++)
#pragma unroll
        for (int j = 0; j < 4; j++) acc[i][j] = 0ULL;

    int ntile = ((STATE + CTXN + l0 + 31) >> 5) + 1;
    if (ntile > 128) ntile = 128;

    for (int st = 0; st < ntile; st++) {
        const int s0 = st * 32;
        __syncthreads();                       // prev PV done with sKV / sS
        {   // K tile -> sKV
            int s = s0 + ldr;
            const float* p = (s < STATE)
                ? cK + ((size_t)(g * STATE + s)) * DH
                : kN + ((size_t)(g * TT + (s - STATE))) * DH;
#pragma unroll
            for (int i = 0; i < 4; i++) {
                int c4 = ldf + 8 * i;
                float4 v = *(const float4*)(p + c4 * 4);
                *(float4*)&sKV[ldr][((c4 + ldr) & 31) * 4] = v;
            }
        }
        __syncthreads();                       // K visible

        // scores: 2q x 2k per thread, packed over d
        unsigned long long s00 = 0, s01 = 0, s10 = 0, s11 = 0;
#pragma unroll 8
        for (int d2 = 0; d2 < 64; d2++) {
            int f = 2 * d2;
            unsigned long long qa = *(const unsigned long long*)&sQ[ty][f];
            unsigned long long qb = *(const unsigned long long*)&sQ[ty + 16][f];
            unsigned long long ka = *(const unsigned long long*)&sKV[tx][swf(tx, f)];
            unsigned long long kb = *(const unsigned long long*)&sKV[tx + 16][swf(tx + 16, f)];
            fma2(s00, qa, ka); fma2(s01, qa, kb);
            fma2(s10, qb, ka); fma2(s11, qb, kb);
        }
        {
            float2 p00 = up2(s00), p01 = up2(s01), p10 = up2(s10), p11 = up2(s11);
            int lA = l0 + ty, lB = lA + 16, cA = s0 + tx, cB = cA + 16;
            sS[ty][tx]           = (cA <= 3968 + lA) ? p00.x + p00.y : -1e30f;
            sS[ty][tx + 16]      = (cB <= 3968 + lA) ? p01.x + p01.y : -1e30f;
            sS[ty + 16][tx]      = (cA <= 3968 + lB) ? p10.x + p10.y : -1e30f;
            sS[ty + 16][tx + 16] = (cB <= 3968 + lB) ? p11.x + p11.y : -1e30f;
        }
        __syncthreads();                       // scores visible; sKV free

        // V tile global loads (latency overlaps softmax below)
        float4 vreg[4];
        {
            int s = s0 + ldr;
            const float* p = (s < STATE)
                ? cV + ((size_t)(g * STATE + s)) * DH
                : vN + ((size_t)(g * TT + (s - STATE))) * DH;
#pragma unroll
            for (int i = 0; i < 4; i++)
                vreg[i] = *(const float4*)(p + (ldf + 8 * i) * 4);
        }
        if (tid < 32) {                        // per-row online softmax
            int r = tid;
            float m = sM[r], mx = m;
            float sv[32];
#pragma unroll
            for (int j = 0; j < 32; j++) { sv[j] = sS[r][j]; mx = fmaxf(mx, sv[j]); }
            float c = __expf(m - mx), sum = 0.0f;
#pragma unroll
            for (int j = 0; j < 32; j++) { float e = __expf(sv[j] - mx); sS[r][j] = e; sum += e; }
            sM[r] = mx; sL[r] = sL[r] * c + sum; sC[r] = c;
        }
#pragma unroll
        for (int i = 0; i < 4; i++) {          // V -> sKV
            int c4 = ldf + 8 * i;
            *(float4*)&sKV[ldr][((c4 + ldr) & 31) * 4] = vreg[i];
        }
        __syncthreads();                       // V + probs + factors visible

        // PV: rows {pr, pr+16}, 8 floats each as 4 f32x2 (d = 2*pd + 32*j)
        {
            unsigned long long c0 = pk2(sC[pr]), c1 = pk2(sC[pr + 16]);
#pragma unroll
            for (int j = 0; j < 4; j++) {
                acc[0][j] = mul2(acc[0][j], c0);
                acc[1][j] = mul2(acc[1][j], c1);
            }
        }
#pragma unroll 4
        for (int kk = 0; kk < 32; kk++) {
            unsigned long long p0 = pk2(sS[pr][kk]);
            unsigned long long p1 = pk2(sS[pr + 16][kk]);
#pragma unroll
            for (int j = 0; j < 4; j++) {
                int f = 2 * pd + 32 * j;
                unsigned long long vv =
                    *(const unsigned long long*)&sKV[kk][swf(kk, f)];
                fma2(acc[0][j], p0, vv);
                fma2(acc[1][j], p1, vv);
            }
        }
    }

    float i0 = 1.0f / sL[pr], i1 = 1.0f / sL[pr + 16];
#pragma unroll
    for (int j = 0; j < 4; j++) {
        int f = 2 * pd + 32 * j;
        float2 a = up2(acc[0][j]);
        float2 b = up2(acc[1][j]);
        a.x *= i0; a.y *= i0; b.x *= i1; b.y *= i1;
        *(float2*)&g_o[(size_t)(l0 + pr) * HID + h * DH + f] = a;
        *(float2*)&g_o[(size_t)(l0 + pr + 16) * HID + h * DH + f] = b;
    }
}

// ---------------- launch ----------------
extern "C" void kernel_launch(void* const* d_in, const int* in_sizes, int n_in,
                              void* d_out, int out_size) {
    const float* x     = (const float*)d_in[0];
    const float* xctx  = (const float*)d_in[1];
    const float* cosq  = (const float*)d_in[2];
    const float* sinq  = (const float*)d_in[3];
    const float* cosk  = (const float*)d_in[4];
    const float* sink  = (const float*)d_in[5];
    const float* cK    = (const float*)d_in[6];
    const float* cV    = (const float*)d_in[7];
    // d_in[8] = causal_mask (unused; computed analytically)
    const float* Wq    = (const float*)d_in[9];
    const float* Wk    = (const float*)d_in[10];
    const float* Wv    = (const float*)d_in[11];
    const float* Wo    = (const float*)d_in[12];
    const float* qw    = (const float*)d_in[13];
    const float* kw    = (const float*)d_in[14];

    float* out  = (float*)d_out;
    float* kOut = out + (size_t)LQ * HID;                 // 524288
    float* vOut = kOut + (size_t)HKV * TT * DH;           // +1048576

    // q projection: [128,4096] = x @ Wq^T
    gemm_k<<<dim3(32, 2, 1), 256>>>(0, x, x, LQ, Wq, Wq, nullptr, HID);
    // k/v projection: [1024,1024] = concat(x_ctx,x) @ {Wk,Wv}^T
    gemm_k<<<dim3(8, 16, 2), 256>>>(1, xctx, x, CTXN, Wk, Wv, nullptr, HKV * DH);
    // norms + rope
    qnorm_k<<<dim3(HQ, LQ), 128>>>(cosq, sinq, qw);
    kvnorm_k<<<dim3(HKV, TT), 128>>>(cosk, sink, kw, kOut, vOut);
    // attention
    attn_k<<<dim3(HQ, 4), 256>>>(cK, cV, kOut, vOut);
    // output projection: [128,4096] = o @ Wo^T
    gemm_k<<<dim3(32, 2, 1), 256>>>(2, nullptr, nullptr, 0, Wo, Wo, out, HID);
}

// round 5
// speedup vs baseline: 1.6703x; 1.6703x over previous
#include <cuda_runtime.h>
#include <cuda_bf16.h>
#include <cstdint>
#include <cstddef>

#define HID   4096
#define LQ    128
#define CTXN  896
#define TT    1024
#define STATE 3072
#define HQ    32
#define HKV   8
#define DH    128
#define SCALE 0.08838834764831845f
#define NEPS  1e-6f

// ---------------- scratch (device globals; no allocation APIs) ----------------
__device__ float g_q [LQ * HID];       // q projection  [L][HQ*D]
__device__ float g_qr[HQ * LQ * DH];   // q normed+roped+scaled [HQ][L][D]
__device__ float g_k [TT * HKV * DH];  // k projection  [T][HKV*D]
__device__ float g_v [TT * HKV * DH];  // v projection  [T][HKV*D]
__device__ float g_o [LQ * HID];       // attention out [L][HQ*D]

// ---------------- packed f32x2 helpers (attention) ----------------
static __device__ __forceinline__ unsigned long long pk2(float x) {
    unsigned long long r; unsigned u = __float_as_uint(x);
    asm("mov.b64 %0, {%1, %1};" : "=l"(r) : "r"(u));
    return r;
}
static __device__ __forceinline__ void fma2(unsigned long long& c,
                                            unsigned long long a,
                                            unsigned long long b) {
    asm("fma.rn.f32x2 %0, %1, %2, %0;" : "+l"(c) : "l"(a), "l"(b));
}
static __device__ __forceinline__ unsigned long long mul2(unsigned long long a,
                                                          unsigned long long b) {
    unsigned long long d;
    asm("mul.rn.f32x2 %0, %1, %2;" : "=l"(d) : "l"(a), "l"(b));
    return d;
}
static __device__ __forceinline__ float2 up2(unsigned long long v) {
    unsigned lo, hi;
    asm("mov.b64 {%0, %1}, %2;" : "=r"(lo), "=r"(hi) : "l"(v));
    return make_float2(__uint_as_float(lo), __uint_as_float(hi));
}

// ---------------- mma.sync helpers (baseline PTX, no 'a' features) ----------------
static __device__ __forceinline__ uint32_t smem_u32(const void* p) {
    uint32_t a;
    asm("{ .reg .u64 t; cvta.to.shared.u64 t, %1; cvt.u32.u64 %0, t; }"
        : "=r"(a) : "l"(p));
    return a;
}
static __device__ __forceinline__ void ldm4(uint32_t* r, uint32_t addr) {
    asm volatile("ldmatrix.sync.aligned.m8n8.x4.shared.b16 {%0,%1,%2,%3}, [%4];"
                 : "=r"(r[0]), "=r"(r[1]), "=r"(r[2]), "=r"(r[3]) : "r"(addr));
}
static __device__ __forceinline__ void mma_bf16(float* c, const uint32_t* a,
                                                uint32_t b0, uint32_t b1) {
    asm volatile(
        "mma.sync.aligned.m16n8k16.row.col.f32.bf16.bf16.f32 "
        "{%0,%1,%2,%3}, {%4,%5,%6,%7}, {%8,%9}, {%0,%1,%2,%3};"
        : "+f"(c[0]), "+f"(c[1]), "+f"(c[2]), "+f"(c[3])
        : "r"(a[0]), "r"(a[1]), "r"(a[2]), "r"(a[3]), "r"(b0), "r"(b1));
}
// split 8 fp32 -> hi (truncated bf16x2 x4) + lo (rounded bf16x2 x4)
static __device__ __forceinline__ void cvt_hilo(float4 f0, float4 f1,
                                                uint4& hi, uint4& lo) {
    uint32_t u0 = __float_as_uint(f0.x), u1 = __float_as_uint(f0.y);
    uint32_t u2 = __float_as_uint(f0.z), u3 = __float_as_uint(f0.w);
    uint32_t u4 = __float_as_uint(f1.x), u5 = __float_as_uint(f1.y);
    uint32_t u6 = __float_as_uint(f1.z), u7 = __float_as_uint(f1.w);
    hi.x = __byte_perm(u0, u1, 0x7632);
    hi.y = __byte_perm(u2, u3, 0x7632);
    hi.z = __byte_perm(u4, u5, 0x7632);
    hi.w = __byte_perm(u6, u7, 0x7632);
    float l0 = f0.x - __uint_as_float(u0 & 0xFFFF0000u);
    float l1 = f0.y - __uint_as_float(u1 & 0xFFFF0000u);
    float l2 = f0.z - __uint_as_float(u2 & 0xFFFF0000u);
    float l3 = f0.w - __uint_as_float(u3 & 0xFFFF0000u);
    float l4 = f1.x - __uint_as_float(u4 & 0xFFFF0000u);
    float l5 = f1.y - __uint_as_float(u5 & 0xFFFF0000u);
    float l6 = f1.z - __uint_as_float(u6 & 0xFFFF0000u);
    float l7 = f1.w - __uint_as_float(u7 & 0xFFFF0000u);
    __nv_bfloat162 p0 = __float22bfloat162_rn(make_float2(l0, l1));
    __nv_bfloat162 p1 = __float22bfloat162_rn(make_float2(l2, l3));
    __nv_bfloat162 p2 = __float22bfloat162_rn(make_float2(l4, l5));
    __nv_bfloat162 p3 = __float22bfloat162_rn(make_float2(l6, l7));
    lo.x = *(uint32_t*)&p0; lo.y = *(uint32_t*)&p1;
    lo.z = *(uint32_t*)&p2; lo.w = *(uint32_t*)&p3;
}

// ============ tensor-core GEMM via mma.sync: C[M,N] = A[M,4096]*B[N,4096]^T ===
// 64x64x32 CTA tile, 256 thr, 8 warps (2m x 4n), warp tile 32x16.
// 3-term bf16 split: Ah*Bh + Al*Bh + Ah*Bl (fp32 accum) -> ~2^-16 precision.
// which: 0 -> C=g_q    1 -> C=(z? g_v:g_k), B=(z? B1:B0)    2 -> C=Cext (A=g_o)
#define GP 40   // smem row pitch in bf16 elements (80B: conflict-free ldmatrix)
__global__ __launch_bounds__(256) void gemm_tc(
    int which,
    const float* __restrict__ A0, const float* __restrict__ A1, int split,
    const float* __restrict__ B0, const float* __restrict__ B1,
    float* __restrict__ Cext, int ldc)
{
    __shared__ __align__(16) uint16_t sAh[2][64 * GP];
    __shared__ __align__(16) uint16_t sAl[2][64 * GP];
    __shared__ __align__(16) uint16_t sBh[2][64 * GP];
    __shared__ __align__(16) uint16_t sBl[2][64 * GP];

    const int tid  = threadIdx.x;
    const int lane = tid & 31;
    const int wid  = tid >> 5;
    const int wm   = wid >> 2;       // 0..1
    const int wn   = wid & 3;        // 0..3
    const int m0   = blockIdx.y * 64;
    const int n0   = blockIdx.x * 64;
    const int z    = blockIdx.z;

    const float* B = z ? B1 : B0;
    float* C;
    if      (which == 0) C = g_q;
    else if (which == 1) C = z ? g_v : g_k;
    else                 C = Cext;

    // global load mapping: row = tid>>2 (0..63), kq = (tid&3)*8
    const int grow = tid >> 2;
    const int kq   = (tid & 3) * 8;
    const int rowA = m0 + grow;
    const float* aPtr = (which == 2) ? (g_o + (size_t)rowA * 4096)
                        : (rowA < split ? A0 + (size_t)rowA * 4096
                                        : A1 + (size_t)(rowA - split) * 4096);
    const float* bPtr = B + (size_t)(n0 + grow) * 4096;
    aPtr += kq; bPtr += kq;
    const uint32_t eoff = (uint32_t)(grow * GP + kq);   // element offset for STS

    // ldmatrix per-thread address parts (element offsets)
    const int mrl  = (lane & 7) + ((lane >> 3) & 1) * 8;   // row-in-16 part
    const int kof  = ((lane >> 4) & 1) * 8;                // k-in-16 part
    const uint32_t aoff = (uint32_t)(((32 * wm + mrl) * GP + kof) * 2);
    const uint32_t boff = (uint32_t)(((16 * wn + mrl) * GP + kof) * 2);

    const uint32_t bAh = smem_u32(&sAh[0][0]);
    const uint32_t bAl = smem_u32(&sAl[0][0]);
    const uint32_t bBh = smem_u32(&sBh[0][0]);
    const uint32_t bBl = smem_u32(&sBl[0][0]);
    const uint32_t stgB = 64 * GP * 2;   // bytes per stage

    float acc[2][2][4];
#pragma unroll
    for (int i = 0; i < 2; i++)
#pragma unroll
        for (int j = 0; j < 2; j++)
#pragma unroll
            for (int e = 0; e < 4; e++) acc[i][j][e] = 0.0f;

    float4 ra0 = *(const float4*)(aPtr);
    float4 ra1 = *(const float4*)(aPtr + 4);
    float4 rb0 = *(const float4*)(bPtr);
    float4 rb1 = *(const float4*)(bPtr + 4);

    const int NK = 4096 / 32;
    for (int ic = 0; ic < NK; ic++) {
        const int s = ic & 1;
        // convert + store to stage s
        {
            uint4 hi, lo;
            cvt_hilo(ra0, ra1, hi, lo);
            *(uint4*)&sAh[s][eoff] = hi;
            *(uint4*)&sAl[s][eoff] = lo;
            cvt_hilo(rb0, rb1, hi, lo);
            *(uint4*)&sBh[s][eoff] = hi;
            *(uint4*)&sBl[s][eoff] = lo;
        }
        // prefetch next chunk (global latency overlaps compute)
        if (ic + 1 < NK) {
            const float* an = aPtr + (ic + 1) * 32;
            const float* bn = bPtr + (ic + 1) * 32;
            ra0 = *(const float4*)(an);
            ra1 = *(const float4*)(an + 4);
            rb0 = *(const float4*)(bn);
            rb1 = *(const float4*)(bn + 4);
        }
        __syncthreads();

        const uint32_t sb = (uint32_t)s * stgB;
#pragma unroll
        for (int ks = 0; ks < 2; ks++) {
            const uint32_t kb = (uint32_t)ks * 32;   // 16 elems * 2B
            uint32_t Ah[2][4], Al[2][4], Bh[4], Bl[4];
            ldm4(Ah[0], bAh + sb + aoff + kb);
            ldm4(Ah[1], bAh + sb + aoff + 16 * GP * 2 + kb);
            ldm4(Al[0], bAl + sb + aoff + kb);
            ldm4(Al[1], bAl + sb + aoff + 16 * GP * 2 + kb);
            ldm4(Bh,    bBh + sb + boff + kb);
            ldm4(Bl,    bBl + sb + boff + kb);
#pragma unroll
            for (int tm = 0; tm < 2; tm++)
#pragma unroll
                for (int tn = 0; tn < 2; tn++) {
                    mma_bf16(acc[tm][tn], Ah[tm], Bh[tn], Bh[tn + 2]);
                    mma_bf16(acc[tm][tn], Al[tm], Bh[tn], Bh[tn + 2]);
                    mma_bf16(acc[tm][tn], Ah[tm], Bl[tn], Bl[tn + 2]);
                }
        }
        // next iter's convert targets the other stage; the sync above also
        // separates this compute from the overwrite 2 iterations later.
    }

    // epilogue
    const int r0 = m0 + 32 * wm + (lane >> 2);
    const int c0 = n0 + 16 * wn + (lane & 3) * 2;
#pragma unroll
    for (int tm = 0; tm < 2; tm++)
#pragma unroll
        for (int tn = 0; tn < 2; tn++) {
            float* p = C + (size_t)(r0 + 16 * tm) * ldc + c0 + 8 * tn;
            *(float2*)p = make_float2(acc[tm][tn][0], acc[tm][tn][1]);
            float* p2 = p + (size_t)8 * ldc;
            *(float2*)p2 = make_float2(acc[tm][tn][2], acc[tm][tn][3]);
        }
}

// ---------------- ane-norm + RoPE + scale for Q ----------------
__global__ __launch_bounds__(128) void qnorm_k(
    const float* __restrict__ cq, const float* __restrict__ sq,
    const float* __restrict__ w)
{
    int h = blockIdx.x, l = blockIdx.y, d = threadIdx.x;
    __shared__ float red[8];
    __shared__ float xs[128];
    float v = g_q[l * HID + h * DH + d];
    float s1 = v, s2 = v * v;
#pragma unroll
    for (int off = 16; off; off >>= 1) {
        s1 += __shfl_down_sync(0xffffffffu, s1, off);
        s2 += __shfl_down_sync(0xffffffffu, s2, off);
    }
    if ((d & 31) == 0) { red[d >> 5] = s1; red[4 + (d >> 5)] = s2; }
    __syncthreads();
    float sum = red[0] + red[1] + red[2] + red[3];
    float sqs = red[4] + red[5] + red[6] + red[7];
    float mean = sum * (1.0f / 128.0f);
    float var  = sqs * (1.0f / 128.0f) - mean * mean;
    float xn = (v - mean) * rsqrtf(var + NEPS) * w[d];
    xs[d] = xn;
    __syncthreads();
    float rot = (d < 64) ? -xs[d + 64] : xs[d - 64];
    g_qr[((size_t)h * LQ + l) * DH + d] =
        (xn * cq[l * DH + d] + rot * sq[l * DH + d]) * SCALE;
}

// ---------------- ane-norm + RoPE for K, transpose K/V -> [HKV][T][D] ----------------
__global__ __launch_bounds__(128) void kvnorm_k(
    const float* __restrict__ ck, const float* __restrict__ sk,
    const float* __restrict__ w,
    float* __restrict__ kOut, float* __restrict__ vOut)
{
    int h = blockIdx.x, t = blockIdx.y, d = threadIdx.x;
    __shared__ float red[8];
    __shared__ float xs[128];
    float v = g_k[t * (HKV * DH) + h * DH + d];
    float s1 = v, s2 = v * v;
#pragma unroll
    for (int off = 16; off; off >>= 1) {
        s1 += __shfl_down_sync(0xffffffffu, s1, off);
        s2 += __shfl_down_sync(0xffffffffu, s2, off);
    }
    if ((d & 31) == 0) { red[d >> 5] = s1; red[4 + (d >> 5)] = s2; }
    __syncthreads();
    float sum = red[0] + red[1] + red[2] + red[3];
    float sqs = red[4] + red[5] + red[6] + red[7];
    float mean = sum * (1.0f / 128.0f);
    float var  = sqs * (1.0f / 128.0f) - mean * mean;
    float xn = (v - mean) * rsqrtf(var + NEPS) * w[d];
    xs[d] = xn;
    __syncthreads();
    float rot = (d < 64) ? -xs[d + 64] : xs[d - 64];
    kOut[((size_t)h * TT + t) * DH + d] = xn * ck[t * DH + d] + rot * sk[t * DH + d];
    vOut[((size_t)h * TT + t) * DH + d] = g_v[t * (HKV * DH) + h * DH + d];
}

// ---------------- Flash attention (fp32, f32x2 inner loops) ----------------
static __device__ __forceinline__ int swf(int r, int f) {  // f even
    return ((((f >> 2) + r) & 31) << 2) | (f & 3);
}
__global__ __launch_bounds__(256) void attn_k(
    const float* __restrict__ cK, const float* __restrict__ cV,
    const float* __restrict__ kN, const float* __restrict__ vN)
{
    const int h = blockIdx.x, qt = blockIdx.y;
    const int g = h >> 2, l0 = qt * 32, tid = threadIdx.x;

    __shared__ float sQ [32][132];
    __shared__ float sKV[32][128];
    __shared__ float sS [32][33];
    __shared__ float sM[32], sL[32], sC[32];

    for (int idx = tid; idx < 32 * 32; idx += 256) {
        int r = idx >> 5, c4 = idx & 31;
        *(float4*)&sQ[r][c4 * 4] =
            *(const float4*)&g_qr[((size_t)h * LQ + l0 + r) * DH + c4 * 4];
    }
    if (tid < 32) { sM[tid] = -1e30f; sL[tid] = 0.0f; }

    const int ldr = tid >> 3, ldf = tid & 7;
    const int ty  = tid >> 4, tx  = tid & 15;
    const int pr  = tid >> 4, pd  = tid & 15;

    unsigned long long acc[2][4];
#pragma unroll
    for (int i = 0; i < 2; i++)
#pragma unroll
        for (int j = 0; j < 4; j++) acc[i][j] = 0ULL;

    int ntile = ((STATE + CTXN + l0 + 31) >> 5) + 1;
    if (ntile > 128) ntile = 128;

    for (int st = 0; st < ntile; st++) {
        const int s0 = st * 32;
        __syncthreads();
        {
            int s = s0 + ldr;
            const float* p = (s < STATE)
                ? cK + ((size_t)(g * STATE + s)) * DH
                : kN + ((size_t)(g * TT + (s - STATE))) * DH;
#pragma unroll
            for (int i = 0; i < 4; i++) {
                int c4 = ldf + 8 * i;
                float4 v = *(const float4*)(p + c4 * 4);
                *(float4*)&sKV[ldr][((c4 + ldr) & 31) * 4] = v;
            }
        }
        __syncthreads();

        unsigned long long s00 = 0, s01 = 0, s10 = 0, s11 = 0;
#pragma unroll 8
        for (int d2 = 0; d2 < 64; d2++) {
            int f = 2 * d2;
            unsigned long long qa = *(const unsigned long long*)&sQ[ty][f];
            unsigned long long qb = *(const unsigned long long*)&sQ[ty + 16][f];
            unsigned long long ka = *(const unsigned long long*)&sKV[tx][swf(tx, f)];
            unsigned long long kb = *(const unsigned long long*)&sKV[tx + 16][swf(tx + 16, f)];
            fma2(s00, qa, ka); fma2(s01, qa, kb);
            fma2(s10, qb, ka); fma2(s11, qb, kb);
        }
        {
            float2 p00 = up2(s00), p01 = up2(s01), p10 = up2(s10), p11 = up2(s11);
            int lA = l0 + ty, lB = lA + 16, cA = s0 + tx, cB = cA + 16;
            sS[ty][tx]           = (cA <= 3968 + lA) ? p00.x + p00.y : -1e30f;
            sS[ty][tx + 16]      = (cB <= 3968 + lA) ? p01.x + p01.y : -1e30f;
            sS[ty + 16][tx]      = (cA <= 3968 + lB) ? p10.x + p10.y : -1e30f;
            sS[ty + 16][tx + 16] = (cB <= 3968 + lB) ? p11.x + p11.y : -1e30f;
        }
        __syncthreads();

        float4 vreg[4];
        {
            int s = s0 + ldr;
            const float* p = (s < STATE)
                ? cV + ((size_t)(g * STATE + s)) * DH
                : vN + ((size_t)(g * TT + (s - STATE))) * DH;
#pragma unroll
            for (int i = 0; i < 4; i++)
                vreg[i] = *(const float4*)(p + (ldf + 8 * i) * 4);
        }
        if (tid < 32) {
            int r = tid;
            float m = sM[r], mx = m;
            float sv[32];
#pragma unroll
            for (int j = 0; j < 32; j++) { sv[j] = sS[r][j]; mx = fmaxf(mx, sv[j]); }
            float c = __expf(m - mx), sum = 0.0f;
#pragma unroll
            for (int j = 0; j < 32; j++) { float e = __expf(sv[j] - mx); sS[r][j] = e; sum += e; }
            sM[r] = mx; sL[r] = sL[r] * c + sum; sC[r] = c;
        }
#pragma unroll
        for (int i = 0; i < 4; i++) {
            int c4 = ldf + 8 * i;
            *(float4*)&sKV[ldr][((c4 + ldr) & 31) * 4] = vreg[i];
        }
        __syncthreads();

        {
            unsigned long long c0 = pk2(sC[pr]), c1 = pk2(sC[pr + 16]);
#pragma unroll
            for (int j = 0; j < 4; j++) {
                acc[0][j] = mul2(acc[0][j], c0);
                acc[1][j] = mul2(acc[1][j], c1);
            }
        }
#pragma unroll 4
        for (int kk = 0; kk < 32; kk++) {
            unsigned long long p0 = pk2(sS[pr][kk]);
            unsigned long long p1 = pk2(sS[pr + 16][kk]);
#pragma unroll
            for (int j = 0; j < 4; j++) {
                int f = 2 * pd + 32 * j;
                unsigned long long vv =
                    *(const unsigned long long*)&sKV[kk][swf(kk, f)];
                fma2(acc[0][j], p0, vv);
                fma2(acc[1][j], p1, vv);
            }
        }
    }

    float i0 = 1.0f / sL[pr], i1 = 1.0f / sL[pr + 16];
#pragma unroll
    for (int j = 0; j < 4; j++) {
        int f = 2 * pd + 32 * j;
        float2 a = up2(acc[0][j]);
        float2 b = up2(acc[1][j]);
        a.x *= i0; a.y *= i0; b.x *= i1; b.y *= i1;
        *(float2*)&g_o[(size_t)(l0 + pr) * HID + h * DH + f] = a;
        *(float2*)&g_o[(size_t)(l0 + pr + 16) * HID + h * DH + f] = b;
    }
}

// ---------------- launch ----------------
extern "C" void kernel_launch(void* const* d_in, const int* in_sizes, int n_in,
                              void* d_out, int out_size) {
    const float* x     = (const float*)d_in[0];
    const float* xctx  = (const float*)d_in[1];
    const float* cosq  = (const float*)d_in[2];
    const float* sinq  = (const float*)d_in[3];
    const float* cosk  = (const float*)d_in[4];
    const float* sink  = (const float*)d_in[5];
    const float* cK    = (const float*)d_in[6];
    const float* cV    = (const float*)d_in[7];
    // d_in[8] = causal_mask (unused; computed analytically)
    const float* Wq    = (const float*)d_in[9];
    const float* Wk    = (const float*)d_in[10];
    const float* Wv    = (const float*)d_in[11];
    const float* Wo    = (const float*)d_in[12];
    const float* qw    = (const float*)d_in[13];
    const float* kw    = (const float*)d_in[14];

    float* out  = (float*)d_out;
    float* kOut = out + (size_t)LQ * HID;
    float* vOut = kOut + (size_t)HKV * TT * DH;

    // q projection: [128,4096] = x @ Wq^T
    gemm_tc<<<dim3(64, 2, 1), 256>>>(0, x, x, LQ, Wq, Wq, nullptr, HID);
    // k/v projection: [1024,1024] = concat(x_ctx,x) @ {Wk,Wv}^T
    gemm_tc<<<dim3(16, 16, 2), 256>>>(1, xctx, x, CTXN, Wk, Wv, nullptr, HKV * DH);
    // norms + rope
    qnorm_k<<<dim3(HQ, LQ), 128>>>(cosq, sinq, qw);
    kvnorm_k<<<dim3(HKV, TT), 128>>>(cosk, sink, kw, kOut, vOut);
    // attention
    attn_k<<<dim3(HQ, 4), 256>>>(cK, cV, kOut, vOut);
    // output projection: [128,4096] = o @ Wo^T
    gemm_tc<<<dim3(64, 2, 1), 256>>>(2, nullptr, nullptr, 1 << 30, Wo, Wo, out, HID);
}

// round 6
// speedup vs baseline: 1.7256x; 1.0331x over previous
#include <cuda_runtime.h>
#include <cuda_bf16.h>
#include <cstdint>
#include <cstddef>

#define HID   4096
#define LQ    128
#define CTXN  896
#define TT    1024
#define STATE 3072
#define HQ    32
#define HKV   8
#define DH    128
#define SCALE 0.08838834764831845f
#define NEPS  1e-6f

// ---------------- scratch (device globals; no allocation APIs) ----------------
__device__ float g_q [LQ * HID];
__device__ float g_qr[HQ * LQ * DH];
__device__ float g_k [TT * HKV * DH];
__device__ float g_v [TT * HKV * DH];
__device__ float g_o [LQ * HID];

// split-bf16 operands (hi = truncated fp32 upper16, lo = rn(f - hi))
__device__ __nv_bfloat16 c_actH[TT * HID];     // concat(xctx, x)
__device__ __nv_bfloat16 c_actL[TT * HID];
__device__ __nv_bfloat16 c_wqH [HID * HID];
__device__ __nv_bfloat16 c_wqL [HID * HID];
__device__ __nv_bfloat16 c_wkH [HKV * DH * HID];
__device__ __nv_bfloat16 c_wkL [HKV * DH * HID];
__device__ __nv_bfloat16 c_wvH [HKV * DH * HID];
__device__ __nv_bfloat16 c_wvL [HKV * DH * HID];
__device__ __nv_bfloat16 c_woH [HID * HID];
__device__ __nv_bfloat16 c_woL [HID * HID];
__device__ __nv_bfloat16 c_goH [LQ * HID];
__device__ __nv_bfloat16 c_goL [LQ * HID];

// ---------------- packed f32x2 helpers (attention) ----------------
static __device__ __forceinline__ unsigned long long pk2(float x) {
    unsigned long long r; unsigned u = __float_as_uint(x);
    asm("mov.b64 %0, {%1, %1};" : "=l"(r) : "r"(u));
    return r;
}
static __device__ __forceinline__ void fma2(unsigned long long& c,
                                            unsigned long long a,
                                            unsigned long long b) {
    asm("fma.rn.f32x2 %0, %1, %2, %0;" : "+l"(c) : "l"(a), "l"(b));
}
static __device__ __forceinline__ unsigned long long mul2(unsigned long long a,
                                                          unsigned long long b) {
    unsigned long long d;
    asm("mul.rn.f32x2 %0, %1, %2;" : "=l"(d) : "l"(a), "l"(b));
    return d;
}
static __device__ __forceinline__ float2 up2(unsigned long long v) {
    unsigned lo, hi;
    asm("mov.b64 {%0, %1}, %2;" : "=r"(lo), "=r"(hi) : "l"(v));
    return make_float2(__uint_as_float(lo), __uint_as_float(hi));
}

// ---------------- mma helpers ----------------
static __device__ __forceinline__ uint32_t smem_u32(const void* p) {
    uint32_t a;
    asm("{ .reg .u64 t; cvta.to.shared.u64 t, %1; cvt.u32.u64 %0, t; }"
        : "=r"(a) : "l"(p));
    return a;
}
static __device__ __forceinline__ void ldm4(uint32_t* r, uint32_t addr) {
    asm volatile("ldmatrix.sync.aligned.m8n8.x4.shared.b16 {%0,%1,%2,%3}, [%4];"
                 : "=r"(r[0]), "=r"(r[1]), "=r"(r[2]), "=r"(r[3]) : "r"(addr));
}
static __device__ __forceinline__ void mma_bf16(float* c, const uint32_t* a,
                                                uint32_t b0, uint32_t b1) {
    asm volatile(
        "mma.sync.aligned.m16n8k16.row.col.f32.bf16.bf16.f32 "
        "{%0,%1,%2,%3}, {%4,%5,%6,%7}, {%8,%9}, {%0,%1,%2,%3};"
        : "+f"(c[0]), "+f"(c[1]), "+f"(c[2]), "+f"(c[3])
        : "r"(a[0]), "r"(a[1]), "r"(a[2]), "r"(a[3]), "r"(b0), "r"(b1));
}
#define CPA16(dst, src) \
    asm volatile("cp.async.cg.shared.global [%0], [%1], 16;" \
                 :: "r"(dst), "l"(src) : "memory")
#define CPA_COMMIT() asm volatile("cp.async.commit_group;" ::: "memory")
#define CPA_WAIT2()  asm volatile("cp.async.wait_group 2;" ::: "memory")

// ---------------- fp32 -> (hi, lo) bf16 split (vectorized x4) ----------------
__global__ __launch_bounds__(256) void cvt_split(
    const float4* __restrict__ src, uint2* __restrict__ hi,
    uint2* __restrict__ lo, int n4)
{
    int i = blockIdx.x * 256 + threadIdx.x;
    if (i >= n4) return;
    float4 f = src[i];
    uint32_t u0 = __float_as_uint(f.x), u1 = __float_as_uint(f.y);
    uint32_t u2 = __float_as_uint(f.z), u3 = __float_as_uint(f.w);
    uint2 h, l;
    h.x = __byte_perm(u0, u1, 0x7632);
    h.y = __byte_perm(u2, u3, 0x7632);
    float l0 = f.x - __uint_as_float(u0 & 0xFFFF0000u);
    float l1 = f.y - __uint_as_float(u1 & 0xFFFF0000u);
    float l2 = f.z - __uint_as_float(u2 & 0xFFFF0000u);
    float l3 = f.w - __uint_as_float(u3 & 0xFFFF0000u);
    __nv_bfloat162 p0 = __float22bfloat162_rn(make_float2(l0, l1));
    __nv_bfloat162 p1 = __float22bfloat162_rn(make_float2(l2, l3));
    l.x = *(uint32_t*)&p0;
    l.y = *(uint32_t*)&p1;
    hi[i] = h; lo[i] = l;
}

// ============ GEMM: C[M,N] = A[M,4096] * B[N,4096]^T (pre-split bf16) ========
// 64x64x32 CTA tile, 256 thr, 8 warps (2m x 4n, warp 32x16), cp.async 4-stage.
// 3-term: Ah*Bh + Al*Bh + Ah*Bl, fp32 accum.
#define GP       40
#define ARR_B    5120u          // 64 rows * 80 B
#define STG_B    20480u         // 4 arrays (Ah, Al, Bh, Bl)
__global__ __launch_bounds__(256) void gemm_bf3(
    const __nv_bfloat16* __restrict__ aH, const __nv_bfloat16* __restrict__ aL,
    const __nv_bfloat16* __restrict__ bH0, const __nv_bfloat16* __restrict__ bL0,
    const __nv_bfloat16* __restrict__ bH1, const __nv_bfloat16* __restrict__ bL1,
    float* __restrict__ C0, float* __restrict__ C1, int ldc)
{
    extern __shared__ __align__(16) char sm[];
    const int tid  = threadIdx.x;
    const int lane = tid & 31;
    const int wid  = tid >> 5;
    const int wm   = wid >> 2;
    const int wn   = wid & 3;
    const int m0   = blockIdx.y * 64;
    const int n0   = blockIdx.x * 64;
    const int z    = blockIdx.z;

    const __nv_bfloat16* bH = z ? bH1 : bH0;
    const __nv_bfloat16* bL = z ? bL1 : bL0;
    float* C = z ? C1 : C0;

    // cp.async mapping: row = tid>>2 (0..63), 16B chunk c4 = tid&3
    const int row = tid >> 2, c4 = tid & 3;
    const __nv_bfloat16* gaH = aH + (size_t)(m0 + row) * 4096 + c4 * 8;
    const __nv_bfloat16* gaL = aL + (size_t)(m0 + row) * 4096 + c4 * 8;
    const __nv_bfloat16* gbH = bH + (size_t)(n0 + row) * 4096 + c4 * 8;
    const __nv_bfloat16* gbL = bL + (size_t)(n0 + row) * 4096 + c4 * 8;

    const uint32_t smBase = smem_u32(sm);
    const uint32_t sOff   = (uint32_t)(row * 80 + c4 * 16);

    // ldmatrix per-thread address parts
    const int mrl = (lane & 7) + ((lane >> 3) & 1) * 8;
    const int kof = ((lane >> 4) & 1) * 8;
    const uint32_t aoff = (uint32_t)(((32 * wm + mrl) * GP + kof) * 2);
    const uint32_t boff = (uint32_t)(((16 * wn + mrl) * GP + kof) * 2);

    float acc[2][2][4];
#pragma unroll
    for (int i = 0; i < 2; i++)
#pragma unroll
        for (int j = 0; j < 2; j++)
#pragma unroll
            for (int e = 0; e < 4; e++) acc[i][j][e] = 0.0f;

    // prologue: stage 0..2
#pragma unroll
    for (int p = 0; p < 3; p++) {
        uint32_t d = smBase + (uint32_t)p * STG_B + sOff;
        int k0 = p * 32;
        CPA16(d,             gaH + k0);
        CPA16(d + ARR_B,     gaL + k0);
        CPA16(d + 2 * ARR_B, gbH + k0);
        CPA16(d + 3 * ARR_B, gbL + k0);
        CPA_COMMIT();
    }

    const int NK = 128;
    for (int ic = 0; ic < NK; ic++) {
        CPA_WAIT2();
        __syncthreads();

        const uint32_t sb = smBase + (uint32_t)(ic & 3) * STG_B;
#pragma unroll
        for (int ks = 0; ks < 2; ks++) {
            const uint32_t kb = (uint32_t)ks * 32;
            uint32_t Ah[2][4], Al[2][4], Bh[4], Bl[4];
            ldm4(Ah[0], sb + aoff + kb);
            ldm4(Ah[1], sb + aoff + 16 * GP * 2 + kb);
            ldm4(Al[0], sb + ARR_B + aoff + kb);
            ldm4(Al[1], sb + ARR_B + aoff + 16 * GP * 2 + kb);
            ldm4(Bh,    sb + 2 * ARR_B + boff + kb);
            ldm4(Bl,    sb + 3 * ARR_B + boff + kb);
#pragma unroll
            for (int tm = 0; tm < 2; tm++)
#pragma unroll
                for (int tn = 0; tn < 2; tn++) {
                    mma_bf16(acc[tm][tn], Ah[tm], Bh[tn], Bh[tn + 2]);
                    mma_bf16(acc[tm][tn], Al[tm], Bh[tn], Bh[tn + 2]);
                    mma_bf16(acc[tm][tn], Ah[tm], Bl[tn], Bl[tn + 2]);
                }
        }

        // refill stage (ic+3)&3 (its previous content was consumed at iter ic-1)
        if (ic + 3 < NK) {
            int k0 = (ic + 3) * 32;
            uint32_t d = smBase + (uint32_t)((ic + 3) & 3) * STG_B + sOff;
            CPA16(d,             gaH + k0);
            CPA16(d + ARR_B,     gaL + k0);
            CPA16(d + 2 * ARR_B, gbH + k0);
            CPA16(d + 3 * ARR_B, gbL + k0);
        }
        CPA_COMMIT();
    }

    // epilogue
    const int r0 = m0 + 32 * wm + (lane >> 2);
    const int c0 = n0 + 16 * wn + (lane & 3) * 2;
#pragma unroll
    for (int tm = 0; tm < 2; tm++)
#pragma unroll
        for (int tn = 0; tn < 2; tn++) {
            float* p = C + (size_t)(r0 + 16 * tm) * ldc + c0 + 8 * tn;
            *(float2*)p = make_float2(acc[tm][tn][0], acc[tm][tn][1]);
            float* p2 = p + (size_t)8 * ldc;
            *(float2*)p2 = make_float2(acc[tm][tn][2], acc[tm][tn][3]);
        }
}

// ---------------- ane-norm + RoPE + scale for Q ----------------
__global__ __launch_bounds__(128) void qnorm_k(
    const float* __restrict__ cq, const float* __restrict__ sq,
    const float* __restrict__ w)
{
    int h = blockIdx.x, l = blockIdx.y, d = threadIdx.x;
    __shared__ float red[8];
    __shared__ float xs[128];
    float v = g_q[l * HID + h * DH + d];
    float s1 = v, s2 = v * v;
#pragma unroll
    for (int off = 16; off; off >>= 1) {
        s1 += __shfl_down_sync(0xffffffffu, s1, off);
        s2 += __shfl_down_sync(0xffffffffu, s2, off);
    }
    if ((d & 31) == 0) { red[d >> 5] = s1; red[4 + (d >> 5)] = s2; }
    __syncthreads();
    float sum = red[0] + red[1] + red[2] + red[3];
    float sqs = red[4] + red[5] + red[6] + red[7];
    float mean = sum * (1.0f / 128.0f);
    float var  = sqs * (1.0f / 128.0f) - mean * mean;
    float xn = (v - mean) * rsqrtf(var + NEPS) * w[d];
    xs[d] = xn;
    __syncthreads();
    float rot = (d < 64) ? -xs[d + 64] : xs[d - 64];
    g_qr[((size_t)h * LQ + l) * DH + d] =
        (xn * cq[l * DH + d] + rot * sq[l * DH + d]) * SCALE;
}

// ---------------- ane-norm + RoPE for K, transpose K/V -> [HKV][T][D] ----------------
__global__ __launch_bounds__(128) void kvnorm_k(
    const float* __restrict__ ck, const float* __restrict__ sk,
    const float* __restrict__ w,
    float* __restrict__ kOut, float* __restrict__ vOut)
{
    int h = blockIdx.x, t = blockIdx.y, d = threadIdx.x;
    __shared__ float red[8];
    __shared__ float xs[128];
    float v = g_k[t * (HKV * DH) + h * DH + d];
    float s1 = v, s2 = v * v;
#pragma unroll
    for (int off = 16; off; off >>= 1) {
        s1 += __shfl_down_sync(0xffffffffu, s1, off);
        s2 += __shfl_down_sync(0xffffffffu, s2, off);
    }
    if ((d & 31) == 0) { red[d >> 5] = s1; red[4 + (d >> 5)] = s2; }
    __syncthreads();
    float sum = red[0] + red[1] + red[2] + red[3];
    float sqs = red[4] + red[5] + red[6] + red[7];
    float mean = sum * (1.0f / 128.0f);
    float var  = sqs * (1.0f / 128.0f) - mean * mean;
    float xn = (v - mean) * rsqrtf(var + NEPS) * w[d];
    xs[d] = xn;
    __syncthreads();
    float rot = (d < 64) ? -xs[d + 64] : xs[d - 64];
    kOut[((size_t)h * TT + t) * DH + d] = xn * ck[t * DH + d] + rot * sk[t * DH + d];
    vOut[((size_t)h * TT + t) * DH + d] = g_v[t * (HKV * DH) + h * DH + d];
}

// ---------------- Flash attention (fp32, f32x2 inner loops) ----------------
static __device__ __forceinline__ int swf(int r, int f) {  // f even
    return ((((f >> 2) + r) & 31) << 2) | (f & 3);
}
__global__ __launch_bounds__(256) void attn_k(
    const float* __restrict__ cK, const float* __restrict__ cV,
    const float* __restrict__ kN, const float* __restrict__ vN)
{
    const int h = blockIdx.x, qt = blockIdx.y;
    const int g = h >> 2, l0 = qt * 32, tid = threadIdx.x;

    __shared__ float sQ [32][132];
    __shared__ float sKV[32][128];
    __shared__ float sS [32][33];
    __shared__ float sM[32], sL[32], sC[32];

    for (int idx = tid; idx < 32 * 32; idx += 256) {
        int r = idx >> 5, c4 = idx & 31;
        *(float4*)&sQ[r][c4 * 4] =
            *(const float4*)&g_qr[((size_t)h * LQ + l0 + r) * DH + c4 * 4];
    }
    if (tid < 32) { sM[tid] = -1e30f; sL[tid] = 0.0f; }

    const int ldr = tid >> 3, ldf = tid & 7;
    const int ty  = tid >> 4, tx  = tid & 15;
    const int pr  = tid >> 4, pd  = tid & 15;

    unsigned long long acc[2][4];
#pragma unroll
    for (int i = 0; i < 2; i++)
#pragma unroll
        for (int j = 0; j < 4; j++) acc[i][j] = 0ULL;

    int ntile = ((STATE + CTXN + l0 + 31) >> 5) + 1;
    if (ntile > 128) ntile = 128;

    for (int st = 0; st < ntile; st++) {
        const int s0 = st * 32;
        __syncthreads();
        {
            int s = s0 + ldr;
            const float* p = (s < STATE)
                ? cK + ((size_t)(g * STATE + s)) * DH
                : kN + ((size_t)(g * TT + (s - STATE))) * DH;
#pragma unroll
            for (int i = 0; i < 4; i++) {
                int c4 = ldf + 8 * i;
                float4 v = *(const float4*)(p + c4 * 4);
                *(float4*)&sKV[ldr][((c4 + ldr) & 31) * 4] = v;
            }
        }
        __syncthreads();

        unsigned long long s00 = 0, s01 = 0, s10 = 0, s11 = 0;
#pragma unroll 8
        for (int d2 = 0; d2 < 64; d2++) {
            int f = 2 * d2;
            unsigned long long qa = *(const unsigned long long*)&sQ[ty][f];
            unsigned long long qb = *(const unsigned long long*)&sQ[ty + 16][f];
            unsigned long long ka = *(const unsigned long long*)&sKV[tx][swf(tx, f)];
            unsigned long long kb = *(const unsigned long long*)&sKV[tx + 16][swf(tx + 16, f)];
            fma2(s00, qa, ka); fma2(s01, qa, kb);
            fma2(s10, qb, ka); fma2(s11, qb, kb);
        }
        {
            float2 p00 = up2(s00), p01 = up2(s01), p10 = up2(s10), p11 = up2(s11);
            int lA = l0 + ty, lB = lA + 16, cA = s0 + tx, cB = cA + 16;
            sS[ty][tx]           = (cA <= 3968 + lA) ? p00.x + p00.y : -1e30f;
            sS[ty][tx + 16]      = (cB <= 3968 + lA) ? p01.x + p01.y : -1e30f;
            sS[ty + 16][tx]      = (cA <= 3968 + lB) ? p10.x + p10.y : -1e30f;
            sS[ty + 16][tx + 16] = (cB <= 3968 + lB) ? p11.x + p11.y : -1e30f;
        }
        __syncthreads();

        float4 vreg[4];
        {
            int s = s0 + ldr;
            const float* p = (s < STATE)
                ? cV + ((size_t)(g * STATE + s)) * DH
                : vN + ((size_t)(g * TT + (s - STATE))) * DH;
#pragma unroll
            for (int i = 0; i < 4; i++)
                vreg[i] = *(const float4*)(p + (ldf + 8 * i) * 4);
        }
        if (tid < 32) {
            int r = tid;
            float m = sM[r], mx = m;
            float sv[32];
#pragma unroll
            for (int j = 0; j < 32; j++) { sv[j] = sS[r][j]; mx = fmaxf(mx, sv[j]); }
            float c = __expf(m - mx), sum = 0.0f;
#pragma unroll
            for (int j = 0; j < 32; j++) { float e = __expf(sv[j] - mx); sS[r][j] = e; sum += e; }
            sM[r] = mx; sL[r] = sL[r] * c + sum; sC[r] = c;
        }
#pragma unroll
        for (int i = 0; i < 4; i++) {
            int c4 = ldf + 8 * i;
            *(float4*)&sKV[ldr][((c4 + ldr) & 31) * 4] = vreg[i];
        }
        __syncthreads();

        {
            unsigned long long c0 = pk2(sC[pr]), c1 = pk2(sC[pr + 16]);
#pragma unroll
            for (int j = 0; j < 4; j++) {
                acc[0][j] = mul2(acc[0][j], c0);
                acc[1][j] = mul2(acc[1][j], c1);
            }
        }
#pragma unroll 4
        for (int kk = 0; kk < 32; kk++) {
            unsigned long long p0 = pk2(sS[pr][kk]);
            unsigned long long p1 = pk2(sS[pr + 16][kk]);
#pragma unroll
            for (int j = 0; j < 4; j++) {
                int f = 2 * pd + 32 * j;
                unsigned long long vv =
                    *(const unsigned long long*)&sKV[kk][swf(kk, f)];
                fma2(acc[0][j], p0, vv);
                fma2(acc[1][j], p1, vv);
            }
        }
    }

    float i0 = 1.0f / sL[pr], i1 = 1.0f / sL[pr + 16];
#pragma unroll
    for (int j = 0; j < 4; j++) {
        int f = 2 * pd + 32 * j;
        float2 a = up2(acc[0][j]);
        float2 b = up2(acc[1][j]);
        a.x *= i0; a.y *= i0; b.x *= i1; b.y *= i1;
        *(float2*)&g_o[(size_t)(l0 + pr) * HID + h * DH + f] = a;
        *(float2*)&g_o[(size_t)(l0 + pr + 16) * HID + h * DH + f] = b;
    }
}

// ---------------- launch ----------------
extern "C" void kernel_launch(void* const* d_in, const int* in_sizes, int n_in,
                              void* d_out, int out_size) {
    const float* x     = (const float*)d_in[0];
    const float* xctx  = (const float*)d_in[1];
    const float* cosq  = (const float*)d_in[2];
    const float* sinq  = (const float*)d_in[3];
    const float* cosk  = (const float*)d_in[4];
    const float* sink  = (const float*)d_in[5];
    const float* cK    = (const float*)d_in[6];
    const float* cV    = (const float*)d_in[7];
    // d_in[8] = causal_mask (unused; computed analytically)
    const float* Wq    = (const float*)d_in[9];
    const float* Wk    = (const float*)d_in[10];
    const float* Wv    = (const float*)d_in[11];
    const float* Wo    = (const float*)d_in[12];
    const float* qw    = (const float*)d_in[13];
    const float* kw    = (const float*)d_in[14];

    float* out  = (float*)d_out;
    float* kOut = out + (size_t)LQ * HID;
    float* vOut = kOut + (size_t)HKV * TT * DH;

    cudaFuncSetAttribute(gemm_bf3, cudaFuncAttributeMaxDynamicSharedMemorySize,
                         81920);

    // device-global symbol addresses (host-side; no allocation)
    __nv_bfloat16 *actH, *actL, *wqH, *wqL, *wkH, *wkL, *wvH, *wvL,
                  *woH, *woL, *goH, *goL;
    cudaGetSymbolAddress((void**)&actH, c_actH);
    cudaGetSymbolAddress((void**)&actL, c_actL);
    cudaGetSymbolAddress((void**)&wqH,  c_wqH);
    cudaGetSymbolAddress((void**)&wqL,  c_wqL);
    cudaGetSymbolAddress((void**)&wkH,  c_wkH);
    cudaGetSymbolAddress((void**)&wkL,  c_wkL);
    cudaGetSymbolAddress((void**)&wvH,  c_wvH);
    cudaGetSymbolAddress((void**)&wvL,  c_wvL);
    cudaGetSymbolAddress((void**)&woH,  c_woH);
    cudaGetSymbolAddress((void**)&woL,  c_woL);
    cudaGetSymbolAddress((void**)&goH,  c_goH);
    cudaGetSymbolAddress((void**)&goL,  c_goL);
    float *gq, *gqr, *gk, *gv, *go;
    cudaGetSymbolAddress((void**)&gq,  g_q);
    cudaGetSymbolAddress((void**)&gqr, g_qr);
    cudaGetSymbolAddress((void**)&gk,  g_k);
    cudaGetSymbolAddress((void**)&gv,  g_v);
    cudaGetSymbolAddress((void**)&go,  g_o);
    (void)gq; (void)gqr; (void)gk; (void)gv;

    auto cvt = [&](const float* s, __nv_bfloat16* h, __nv_bfloat16* l, int n) {
        int n4 = n / 4;
        cvt_split<<<(n4 + 255) / 256, 256>>>(
            (const float4*)s, (uint2*)h, (uint2*)l, n4);
    };

    // split conversions (every call; deterministic)
    cvt(Wq, wqH, wqL, HID * HID);
    cvt(Wk, wkH, wkL, HKV * DH * HID);
    cvt(Wv, wvH, wvL, HKV * DH * HID);
    cvt(Wo, woH, woL, HID * HID);
    cvt(xctx, actH, actL, CTXN * HID);
    cvt(x, actH + (size_t)CTXN * HID, actL + (size_t)CTXN * HID, LQ * HID);

    // q projection: A = act rows 896.., B = Wq
    gemm_bf3<<<dim3(64, 2, 1), 256, 81920>>>(
        actH + (size_t)CTXN * HID, actL + (size_t)CTXN * HID,
        wqH, wqL, wqH, wqL, gq, gq, HID);
    // k/v projection: A = full act, B = Wk (z=0) / Wv (z=1)
    gemm_bf3<<<dim3(16, 16, 2), 256, 81920>>>(
        actH, actL, wkH, wkL, wvH, wvL, gk, gv, HKV * DH);
    // norms + rope
    qnorm_k<<<dim3(HQ, LQ), 128>>>(cosq, sinq, qw);
    kvnorm_k<<<dim3(HKV, TT), 128>>>(cosk, sink, kw, kOut, vOut);
    // attention
    attn_k<<<dim3(HQ, 4), 256>>>(cK, cV, kOut, vOut);
    // o conversion + output projection
    cvt(go, goH, goL, LQ * HID);
    gemm_bf3<<<dim3(64, 2, 1), 256, 81920>>>(
        goH, goL, woH, woL, woH, woL, out, out, HID);
}